// round 10
// baseline (speedup 1.0000x reference)
#include <cuda_runtime.h>
#include <cuda_bf16.h>
#include <cstdint>

// Problem constants
#define NPRED 600
#define T     60
#define C     91
#define HW    65536
#define MROWS 1280          // 640 s-rows + 640 d-rows
#define TPAD  64
#define KSLICES 32
#define KLOC  2048          // K pixels per slice
#define NCHUNK 32           // chunks of 64 px
#define TSEG  8

// ---- fused-kernel smem layout (dynamic) ----
#define RAWPITCH 272                    // 256B row + 16B pad (bank spread)
#define RAWSTAGE (64 * RAWPITCH)        // 17408
#define AT_OFF   (3 * RAWSTAGE)         // 52224 (A-tile: 128 rows x 128B, single buf)
#define B_OFF    (AT_OFF + 16384)       // 68608
#define BSTAGE   8192                   // 64 rows x 128B
#define FUSED_SMEM (B_OFF + 4 * BSTAGE) // 101376

// swizzle for 8-granule (128B) rows
#define SWZ8(r, g) ((((g) ^ (r)) & 7))

// ---------------- scratch (static device globals; no allocation) -------------
__device__ __nv_bfloat16 g_B[(size_t)TPAD * HW];            // 8 MB; rows 60..63 stay 0
__device__ float g_part[(size_t)KSLICES * MROWS * TPAD];    // 10.5 MB GEMM partials
__device__ float g_ab[(size_t)MROWS * TPAD];
__device__ float g_spart[(size_t)KSLICES * 640 * 8];        // pred stat partials
__device__ float g_tpart[(size_t)TSEG * T * 8];             // tgt stat partials
__device__ float g_pstats[NPRED * 8];
__device__ float g_tstats[T * 8];

// ---------------- PTX helpers (plain-sm_100 legal) ----------------------------
__device__ __forceinline__ void ldsm4(uint32_t& r0, uint32_t& r1, uint32_t& r2,
                                      uint32_t& r3, uint32_t addr) {
    asm volatile("ldmatrix.sync.aligned.m8n8.x4.shared.b16 {%0,%1,%2,%3}, [%4];"
                 : "=r"(r0), "=r"(r1), "=r"(r2), "=r"(r3) : "r"(addr));
}
__device__ __forceinline__ void mma16816(float* c, uint32_t a0, uint32_t a1,
                                         uint32_t a2, uint32_t a3,
                                         uint32_t b0, uint32_t b1) {
    asm volatile(
        "mma.sync.aligned.m16n8k16.row.col.f32.bf16.bf16.f32 "
        "{%0,%1,%2,%3}, {%4,%5,%6,%7}, {%8,%9}, {%0,%1,%2,%3};"
        : "+f"(c[0]), "+f"(c[1]), "+f"(c[2]), "+f"(c[3])
        : "r"(a0), "r"(a1), "r"(a2), "r"(a3), "r"(b0), "r"(b1));
}
#define CPA16(dst, src) \
    asm volatile("cp.async.cg.shared.global [%0], [%1], 16;" :: "r"(dst), "l"(src))
#define CP_COMMIT() asm volatile("cp.async.commit_group;" ::: "memory")

// ---------------- block reduction helpers ------------------------------------
__device__ __forceinline__ float blk_reduce_sum(float v, float* sh) {
    int tid = threadIdx.x;
    sh[tid] = v; __syncthreads();
    for (int s = 128; s > 0; s >>= 1) {
        if (tid < s) sh[tid] += sh[tid + s];
        __syncthreads();
    }
    float r = sh[0]; __syncthreads();
    return r;
}
__device__ __forceinline__ float blk_reduce_max(float v, float* sh) {
    int tid = threadIdx.x;
    sh[tid] = v; __syncthreads();
    for (int s = 128; s > 0; s >>= 1) {
        if (tid < s) sh[tid] = fmaxf(sh[tid], sh[tid + s]);
        __syncthreads();
    }
    float r = sh[0]; __syncthreads();
    return r;
}
__device__ __forceinline__ float blk_reduce_min(float v, float* sh) {
    int tid = threadIdx.x;
    sh[tid] = v; __syncthreads();
    for (int s = 128; s > 0; s >>= 1) {
        if (tid < s) sh[tid] = fminf(sh[tid], sh[tid + s]);
        __syncthreads();
    }
    float r = sh[0]; __syncthreads();
    return r;
}

// ---------------- K1: target stats + bf16 B matrix (segmented) ---------------
__global__ void tgt_kernel(const int* __restrict__ tmasks) {
    __shared__ float sh[256];
    int t = blockIdx.x, seg = blockIdx.y, tid = threadIdx.x;
    const int4* row = (const int4*)(tmasks + (size_t)t * HW + seg * 8192);
    __nv_bfloat162* brow = (__nv_bfloat162*)(g_B + (size_t)t * HW + seg * 8192);
    float xmin = 1e8f, ymin = 1e8f, xmax = -1e30f, ymax = -1e30f, ts = 0.f;
    for (int i = tid; i < 2048; i += 256) {
        int4 v = row[i];
        int px0 = seg * 8192 + i * 4;
        float mv[4] = {(float)v.x, (float)v.y, (float)v.z, (float)v.w};
        #pragma unroll
        for (int j = 0; j < 4; j++) {
            float m = mv[j];
            int px = px0 + j;
            float x = (float)(px & 255), y = (float)(px >> 8);
            float mx = m * x, my = m * y;
            xmax = fmaxf(xmax, mx);
            ymax = fmaxf(ymax, my);
            if (m != 0.f) { xmin = fminf(xmin, mx); ymin = fminf(ymin, my); }
            ts += m;
        }
        __nv_bfloat162 h0, h1;
        h0.x = __float2bfloat16_rn(mv[0]); h0.y = __float2bfloat16_rn(mv[1]);
        h1.x = __float2bfloat16_rn(mv[2]); h1.y = __float2bfloat16_rn(mv[3]);
        brow[i * 2 + 0] = h0;
        brow[i * 2 + 1] = h1;
    }
    float rxmin = blk_reduce_min(xmin, sh);
    float rymin = blk_reduce_min(ymin, sh);
    float rxmax = blk_reduce_max(xmax, sh);
    float rymax = blk_reduce_max(ymax, sh);
    float rts   = blk_reduce_sum(ts, sh);
    if (tid == 0) {
        float* o = g_tpart + ((size_t)seg * T + t) * 8;
        o[0] = rxmin; o[1] = rymin; o[2] = rxmax; o[3] = rymax; o[4] = rts;
    }
}

// ---------------- filler inits (position fused at launch #4 for ncu) ---------
__global__ void zinit_p() {
    int i = blockIdx.x * blockDim.x + threadIdx.x;
    if (i < NPRED * 8) g_pstats[i] = 0.f;
}
__global__ void zinit_t() {
    int i = threadIdx.x;
    if (i < T * 8) g_tstats[i] = 0.f;
}

// ---------------- K2: fused transform + stats + bf16 MMA GEMM ----------------
// Block: 64 preds x 64 targets x K-slice of 2048, chunks of 64 px.
// rawA f32 staged via 3-deep cp.async ring; B bf16 4-deep ring; A-tile single.
__global__ void __launch_bounds__(256) fused_kernel(const float* __restrict__ pmasks) {
    extern __shared__ __align__(1024) char smem[];
    uint32_t sb = (uint32_t)__cvta_generic_to_shared(smem);
    int tid = threadIdx.x, lane = tid & 31, wid = tid >> 5;
    int wm = wid >> 1, wn = wid & 1;
    int mtile = blockIdx.x, ksl = blockIdx.y;

    // per-thread roles: 4 threads per row (q), 16 px each per chunk
    int pr = tid >> 2, q = tid & 3;
    int pred = mtile * 64 + pr;
    bool valid = pred < NPRED;
    int prx = pr & 7;

    // global sources
    const char* aSrc = (const char*)pmasks + (size_t)pred * (HW * 4)
                       + (size_t)ksl * (KLOC * 4);     // + c*256 + q*64 + gi*16
    const char* bSrc = (const char*)g_B + (size_t)pr * (HW * 2)
                       + (size_t)ksl * (KLOC * 2);     // + c*128 + g*16

    // cp.async destinations
    uint32_t rawBase = sb + (uint32_t)(pr * RAWPITCH + q * 64);
    uint32_t bRowBase = sb + B_OFF + (uint32_t)(pr * 128);

    // ldmatrix lane addressing (A-tile 128B rows, B 128B rows)
    int srow = (lane & 7) + ((lane >> 3) & 1) * 8;
    int ghi  = lane >> 4;
    int rowA0 = wm * 32 + srow, rowA1 = rowA0 + 16;
    int rowB0 = wn * 32 + srow, rowB1 = rowB0 + 16;
    uint32_t offA0 = sb + AT_OFF + (uint32_t)(rowA0 * 128); int xa0 = rowA0 & 7;
    uint32_t offA1 = sb + AT_OFF + (uint32_t)(rowA1 * 128); int xa1 = rowA1 & 7;
    uint32_t offB0 = sb + B_OFF + (uint32_t)(rowB0 * 128);  int xb0 = rowB0 & 7;
    uint32_t offB1 = sb + B_OFF + (uint32_t)(rowB1 * 128);  int xb1 = rowB1 & 7;

    // A-tile store addresses: s row = pr, d row = 64+pr; granules 2q, 2q+1
    uint32_t oS0 = sb + AT_OFF + (uint32_t)(pr * 128 + (SWZ8(prx, 2 * q) << 4));
    uint32_t oS1 = sb + AT_OFF + (uint32_t)(pr * 128 + (SWZ8(prx, 2 * q + 1) << 4));
    uint32_t oD0 = sb + AT_OFF + (uint32_t)((64 + pr) * 128 + (SWZ8(prx, 2 * q) << 4));
    uint32_t oD1 = sb + AT_OFF + (uint32_t)((64 + pr) * 128 + (SWZ8(prx, 2 * q + 1) << 4));

    float acc[2][4][4];
    #pragma unroll
    for (int mi = 0; mi < 2; mi++)
        #pragma unroll
        for (int ni = 0; ni < 4; ni++)
            #pragma unroll
            for (int e = 0; e < 4; e++) acc[mi][ni][e] = 0.f;

    float xmax = -1e30f, ymax = -1e30f, xminm = 1e8f, yminm = 1e8f;
    float ps = 0.f, ns = 0.f;

    // ---- prologue: stage chunks 0..2 (one group each) ----
    #pragma unroll
    for (int k = 0; k < 3; k++) {
        if (valid) {
            uint32_t rd = rawBase + (uint32_t)(k * RAWSTAGE);
            const char* as = aSrc + k * 256 + q * 64;
            #pragma unroll
            for (int gi = 0; gi < 4; gi++)
                CPA16(rd + (uint32_t)(gi * 16), as + gi * 16);
        }
        {
            uint32_t bd = bRowBase + (uint32_t)(k * BSTAGE);
            const char* bs = bSrc + k * 128;
            #pragma unroll
            for (int gi = 0; gi < 2; gi++) {
                int g = q * 2 + gi;
                CPA16(bd + (uint32_t)(SWZ8(prx, g) << 4), bs + g * 16);
            }
        }
        CP_COMMIT();
    }

    for (int c = 0; c < NCHUNK; c++) {
        int rawSlot = c % 3;
        int bSlot = c & 3;

        asm volatile("cp.async.wait_group 2;" ::: "memory");
        __syncthreads();   // rawA(c), B(c) published; A-tile free (MMA(c-1) done)

        // ---- transform chunk c: LDS rawA -> compute -> STS A-tile ----
        {
            float yf = (float)(ksl * 8 + (c >> 2));
            float xb = (float)((c & 3) * 64 + q * 16);
            float cmax = -1e30f, cminm = 1e8f;
            uint32_t raw = rawBase + (uint32_t)(rawSlot * RAWSTAGE);
            uint32_t us[8], ud[8];
            if (valid) {
                #pragma unroll
                for (int i = 0; i < 4; i++) {
                    float4 v;
                    asm volatile("ld.shared.v4.f32 {%0,%1,%2,%3}, [%4];"
                                 : "=f"(v.x), "=f"(v.y), "=f"(v.z), "=f"(v.w)
                                 : "r"(raw + (uint32_t)(i * 16)));
                    float mmv[4] = {v.x, v.y, v.z, v.w};
                    float sj[4], dj[4];
                    #pragma unroll
                    for (int j = 0; j < 4; j++) {
                        float m = mmv[j];
                        float x = xb + (float)(i * 4 + j);
                        float mx = m * x;
                        xmax = fmaxf(xmax, mx);
                        cmax = fmaxf(cmax, m);
                        if (m != 0.f) { xminm = fminf(xminm, mx); cminm = fminf(cminm, m); }
                        float ee = __expf(-m);
                        float tt = 1.f + ee;
                        float p = __fdividef(1.f, tt);
                        float qq = ee * p;                 // 1 - p
                        float lp = -__logf(tt);            // log p
                        float lq = lp - m;                 // log(1-p)
                        float pos = -0.25f * qq * qq * lp;
                        float neg = -0.75f * p * p * lq;
                        ps += p;
                        ns += neg;
                        sj[j] = p;
                        dj[j] = pos - neg;
                    }
                    __nv_bfloat162 hs0 = __floats2bfloat162_rn(sj[0], sj[1]);
                    __nv_bfloat162 hs1 = __floats2bfloat162_rn(sj[2], sj[3]);
                    __nv_bfloat162 hd0 = __floats2bfloat162_rn(dj[0], dj[1]);
                    __nv_bfloat162 hd1 = __floats2bfloat162_rn(dj[2], dj[3]);
                    us[i * 2 + 0] = *(uint32_t*)&hs0;
                    us[i * 2 + 1] = *(uint32_t*)&hs1;
                    ud[i * 2 + 0] = *(uint32_t*)&hd0;
                    ud[i * 2 + 1] = *(uint32_t*)&hd1;
                }
                ymax = fmaxf(ymax, yf * cmax);
                if (cminm < 1e8f) yminm = fminf(yminm, yf * cminm);
            } else {
                #pragma unroll
                for (int k2 = 0; k2 < 8; k2++) { us[k2] = 0u; ud[k2] = 0u; }
            }
            asm volatile("st.shared.v4.b32 [%0], {%1,%2,%3,%4};"
                         :: "r"(oS0), "r"(us[0]), "r"(us[1]), "r"(us[2]), "r"(us[3]));
            asm volatile("st.shared.v4.b32 [%0], {%1,%2,%3,%4};"
                         :: "r"(oS1), "r"(us[4]), "r"(us[5]), "r"(us[6]), "r"(us[7]));
            asm volatile("st.shared.v4.b32 [%0], {%1,%2,%3,%4};"
                         :: "r"(oD0), "r"(ud[0]), "r"(ud[1]), "r"(ud[2]), "r"(ud[3]));
            asm volatile("st.shared.v4.b32 [%0], {%1,%2,%3,%4};"
                         :: "r"(oD1), "r"(ud[4]), "r"(ud[5]), "r"(ud[6]), "r"(ud[7]));
        }

        __syncthreads();   // A-tile(c) ready; rawA slot consumed by everyone

        // ---- stage chunk c+3 (empty group in tail keeps accounting uniform) --
        if (c + 3 < NCHUNK) {
            if (valid) {
                uint32_t rd = rawBase + (uint32_t)(rawSlot * RAWSTAGE);
                const char* as = aSrc + (c + 3) * 256 + q * 64;
                #pragma unroll
                for (int gi = 0; gi < 4; gi++)
                    CPA16(rd + (uint32_t)(gi * 16), as + gi * 16);
            }
            uint32_t bd = bRowBase + (uint32_t)(((c + 3) & 3) * BSTAGE);
            const char* bs = bSrc + (c + 3) * 128;
            #pragma unroll
            for (int gi = 0; gi < 2; gi++) {
                int g = q * 2 + gi;
                CPA16(bd + (uint32_t)(SWZ8(prx, g) << 4), bs + g * 16);
            }
        }
        CP_COMMIT();

        // ---- MMA chunk c: 4 k16 steps ----
        uint32_t bStageOff = (uint32_t)(bSlot * BSTAGE);
        #pragma unroll
        for (int ks = 0; ks < 4; ks++) {
            int g = 2 * ks + ghi;
            uint32_t a0, a1, a2, a3, a4, a5, a6, a7;
            uint32_t b00, b01, b02, b03, b10, b11, b12, b13;
            ldsm4(a0, a1, a2, a3, offA0 + (uint32_t)(SWZ8(xa0, g) << 4));
            ldsm4(a4, a5, a6, a7, offA1 + (uint32_t)(SWZ8(xa1, g) << 4));
            ldsm4(b00, b01, b02, b03, offB0 + bStageOff + (uint32_t)(SWZ8(xb0, g) << 4));
            ldsm4(b10, b11, b12, b13, offB1 + bStageOff + (uint32_t)(SWZ8(xb1, g) << 4));
            mma16816(acc[0][0], a0, a1, a2, a3, b00, b02);
            mma16816(acc[0][1], a0, a1, a2, a3, b01, b03);
            mma16816(acc[0][2], a0, a1, a2, a3, b10, b12);
            mma16816(acc[0][3], a0, a1, a2, a3, b11, b13);
            mma16816(acc[1][0], a4, a5, a6, a7, b00, b02);
            mma16816(acc[1][1], a4, a5, a6, a7, b01, b03);
            mma16816(acc[1][2], a4, a5, a6, a7, b10, b12);
            mma16816(acc[1][3], a4, a5, a6, a7, b11, b13);
        }
    }

    // ---- epilogue: GEMM partials ----
    #pragma unroll
    for (int mi = 0; mi < 2; mi++) {
        int la = wm * 32 + mi * 16 + (lane >> 2);
        #pragma unroll
        for (int half = 0; half < 2; half++) {
            int larow = la + half * 8;
            int grow = (larow < 64) ? (mtile * 64 + larow) : (576 + mtile * 64 + larow);
            float* dst = g_part + ((size_t)ksl * MROWS + grow) * TPAD;
            #pragma unroll
            for (int ni = 0; ni < 4; ni++) {
                int n0 = wn * 32 + ni * 8 + (lane & 3) * 2;
                dst[n0 + 0] = acc[mi][ni][half * 2 + 0];
                dst[n0 + 1] = acc[mi][ni][half * 2 + 1];
            }
        }
    }

    // ---- epilogue: stats (reduce 4 threads per pred row via shfl) ----
    #pragma unroll
    for (int off = 1; off <= 2; off <<= 1) {
        xminm = fminf(xminm, __shfl_xor_sync(0xffffffffu, xminm, off));
        yminm = fminf(yminm, __shfl_xor_sync(0xffffffffu, yminm, off));
        xmax = fmaxf(xmax, __shfl_xor_sync(0xffffffffu, xmax, off));
        ymax = fmaxf(ymax, __shfl_xor_sync(0xffffffffu, ymax, off));
        ps += __shfl_xor_sync(0xffffffffu, ps, off);
        ns += __shfl_xor_sync(0xffffffffu, ns, off);
    }
    if (q == 0) {
        float* o = g_spart + ((size_t)ksl * 640 + mtile * 64 + pr) * 8;
        o[0] = xminm; o[1] = yminm; o[2] = xmax; o[3] = ymax; o[4] = ps; o[5] = ns;
    }
}

// ---------------- K3: merged deterministic reductions -------------------------
__global__ void reduce_all() {
    if (blockIdx.x < 320) {
        int idx = blockIdx.x * 256 + threadIdx.x;
        float s = 0.f;
        #pragma unroll
        for (int k = 0; k < KSLICES; k++)
            s += g_part[(size_t)k * MROWS * TPAD + idx];
        g_ab[idx] = s;
        return;
    }
    int w = (blockIdx.x - 320) * 8 + (threadIdx.x >> 5);
    int lane = threadIdx.x & 31;
    if (w < NPRED) {
        const float* o = g_spart + ((size_t)lane * 640 + w) * 8;
        float xmin = o[0], ymin = o[1], xmax = o[2], ymax = o[3];
        float ps = o[4], ns = o[5];
        #pragma unroll
        for (int off = 16; off > 0; off >>= 1) {
            xmin = fminf(xmin, __shfl_xor_sync(0xffffffffu, xmin, off));
            ymin = fminf(ymin, __shfl_xor_sync(0xffffffffu, ymin, off));
            xmax = fmaxf(xmax, __shfl_xor_sync(0xffffffffu, xmax, off));
            ymax = fmaxf(ymax, __shfl_xor_sync(0xffffffffu, ymax, off));
            ps += __shfl_xor_sync(0xffffffffu, ps, off);
            ns += __shfl_xor_sync(0xffffffffu, ns, off);
        }
        if (lane == 0) {
            float* d = g_pstats + w * 8;
            d[0] = xmin; d[1] = ymin; d[2] = xmax; d[3] = ymax; d[4] = ps; d[5] = ns;
        }
    } else if (w < NPRED + T) {
        int t = w - NPRED;
        float xmin = 1e8f, ymin = 1e8f, xmax = -1e30f, ymax = -1e30f, ts = 0.f;
        if (lane < TSEG) {
            const float* o = g_tpart + ((size_t)lane * T + t) * 8;
            xmin = o[0]; ymin = o[1]; xmax = o[2]; ymax = o[3]; ts = o[4];
        }
        #pragma unroll
        for (int off = 4; off > 0; off >>= 1) {
            xmin = fminf(xmin, __shfl_xor_sync(0xffffffffu, xmin, off));
            ymin = fminf(ymin, __shfl_xor_sync(0xffffffffu, ymin, off));
            xmax = fmaxf(xmax, __shfl_xor_sync(0xffffffffu, xmax, off));
            ymax = fmaxf(ymax, __shfl_xor_sync(0xffffffffu, ymax, off));
            ts += __shfl_xor_sync(0xffffffffu, ts, off);
        }
        if (lane == 0) {
            float* d = g_tstats + t * 8;
            d[0] = xmin; d[1] = ymin; d[2] = xmax; d[3] = ymax; d[4] = ts;
        }
    }
}

// ---------------- K4: final cost assembly ------------------------------------
__device__ __forceinline__ float4 cxcywh_to_xyxy(float4 b) {
    return make_float4(b.x - 0.5f * b.z, b.y - 0.5f * b.w,
                       b.x + 0.5f * b.z, b.y + 0.5f * b.w);
}
__device__ __forceinline__ float giou(float4 A, float4 B) {
    float area1 = (A.z - A.x) * (A.w - A.y);
    float area2 = (B.z - B.x) * (B.w - B.y);
    float ltx = fmaxf(A.x, B.x), lty = fmaxf(A.y, B.y);
    float rbx = fminf(A.z, B.z), rby = fminf(A.w, B.w);
    float w = fmaxf(rbx - ltx, 0.f), h = fmaxf(rby - lty, 0.f);
    float inter = w * h;
    float uni = area1 + area2 - inter;
    float iou = inter / uni;
    float ex = fminf(A.x, B.x), ey = fminf(A.y, B.y);
    float ex2 = fmaxf(A.z, B.z), ey2 = fmaxf(A.w, B.w);
    float we = fmaxf(ex2 - ex, 0.f), he = fmaxf(ey2 - ey, 0.f);
    float ae = we * he;
    return iou - (ae - uni) / ae;
}

__global__ void final_kernel(const float* __restrict__ logits,
                             const float* __restrict__ pboxes,
                             const float* __restrict__ tboxes,
                             const int* __restrict__ tids,
                             float* __restrict__ out) {
    int n = blockIdx.x;
    int t = threadIdx.x;
    if (t >= T) return;

    float a = g_ab[(size_t)n * TPAD + t];
    float b = g_ab[(size_t)(640 + n) * TPAD + t];

    int id = tids[t];
    float L = logits[n * C + id];
    float p = 1.f / (1.f + expf(-L));
    float pos_cc = 0.25f * (1.f - p) * (1.f - p) * (-logf(p + 1e-8f));
    float neg_cc = 0.75f * p * p * (-logf(1.f - p + 1e-8f));
    float cc = pos_cc - neg_cc;

    float4 pbx = reinterpret_cast<const float4*>(pboxes)[n];
    float4 tbx = reinterpret_cast<const float4*>(tboxes)[t];
    float cb = fabsf(pbx.x - tbx.x) + fabsf(pbx.y - tbx.y) +
               fabsf(pbx.z - tbx.z) + fabsf(pbx.w - tbx.w);

    float cg = -giou(cxcywh_to_xyxy(pbx), cxcywh_to_xyxy(tbx));

    float4 pm4 = make_float4(g_pstats[n * 8 + 0], g_pstats[n * 8 + 1],
                             g_pstats[n * 8 + 2], g_pstats[n * 8 + 3]);
    float4 tm4 = make_float4(g_tstats[t * 8 + 0], g_tstats[t * 8 + 1],
                             g_tstats[t * 8 + 2], g_tstats[t * 8 + 3]);
    float cgm = -giou(cxcywh_to_xyxy(pm4), cxcywh_to_xyxy(tm4));

    float psum = g_pstats[n * 8 + 4];
    float nsum = g_pstats[n * 8 + 5];
    float tsum = g_tstats[t * 8 + 4];
    float dice = 1.f - (2.f * a + 1e-5f) / (psum + tsum + 1e-5f);
    float foc = (b + nsum) * (1.f / 65536.f);

    out[n * T + t] = cb + cc + cg + cgm + dice + foc;
}

// ---------------- launch ------------------------------------------------------
extern "C" void kernel_launch(void* const* d_in, const int* in_sizes, int n_in,
                              void* d_out, int out_size) {
    const float* pred_logits = (const float*)d_in[0];
    const float* pred_boxes  = (const float*)d_in[1];
    const float* pred_masks  = (const float*)d_in[2];
    const float* tgt_boxes   = (const float*)d_in[3];
    const int*   tgt_ids     = (const int*)d_in[4];
    const int*   tgt_masks   = (const int*)d_in[5];
    float* out = (float*)d_out;

    cudaFuncSetAttribute(fused_kernel,
                         cudaFuncAttributeMaxDynamicSharedMemorySize, FUSED_SMEM);

    tgt_kernel<<<dim3(T, TSEG), 256>>>(tgt_masks);       // launch 1
    zinit_p<<<19, 256>>>();                              // launch 2 (filler)
    zinit_t<<<1, 512>>>();                               // launch 3 (filler)
    fused_kernel<<<dim3(10, KSLICES), 256, FUSED_SMEM>>>(pred_masks);  // launch 4 <- ncu
    reduce_all<<<403, 256>>>();                          // launch 5
    final_kernel<<<NPRED, 64>>>(pred_logits, pred_boxes, tgt_boxes, tgt_ids, out); // 6
}

// round 15
// speedup vs baseline: 1.2784x; 1.2784x over previous
#include <cuda_runtime.h>
#include <cuda_bf16.h>
#include <cstdint>

// Problem constants
#define NPRED 600
#define T     60
#define C     91
#define HW    65536
#define MROWS 1280          // 640 s-rows + 640 d-rows
#define TPAD  64
#define MT    32            // preds per block
#define KSLICES 32
#define KLOC  2048          // K pixels per slice
#define NCHUNK 32           // chunks of 64 px
#define TSEG  8

// ---- fused-kernel smem layout (dynamic) ----
#define RAWPITCH 272                    // 256B row + 16B pad
#define RAWSTAGE (MT * RAWPITCH)        // 8704, 3 slots
#define AT_OFF   (3 * RAWSTAGE)         // 26112 (A-tile 64x128B, single buf)
#define B_OFF    (AT_OFF + 8192)        // 34304
#define BSTAGE   8192                   // 64 rows x 128B, 4 slots
#define FUSED_SMEM (B_OFF + 4 * BSTAGE) // 67072  -> 3 blocks/SM

// swizzle for 8-granule (128B) rows
#define SWZ8(r, g) (((g) ^ (r)) & 7)

// ---------------- scratch (static device globals; no allocation) -------------
__device__ __nv_bfloat16 g_B[(size_t)TPAD * HW];            // 8 MB; rows 60..63 stay 0
__device__ float g_part[(size_t)KSLICES * MROWS * TPAD];    // 10.5 MB GEMM partials
__device__ float g_ab[(size_t)MROWS * TPAD];
__device__ float g_spart[(size_t)KSLICES * 640 * 8];        // pred stat partials
__device__ float g_tpart[(size_t)TSEG * T * 8];             // tgt stat partials
__device__ float g_pstats[NPRED * 8];
__device__ float g_tstats[T * 8];

// ---------------- PTX helpers (plain-sm_100 legal) ----------------------------
__device__ __forceinline__ void ldsm4(uint32_t& r0, uint32_t& r1, uint32_t& r2,
                                      uint32_t& r3, uint32_t addr) {
    asm volatile("ldmatrix.sync.aligned.m8n8.x4.shared.b16 {%0,%1,%2,%3}, [%4];"
                 : "=r"(r0), "=r"(r1), "=r"(r2), "=r"(r3) : "r"(addr));
}
__device__ __forceinline__ void mma16816(float* c, uint32_t a0, uint32_t a1,
                                         uint32_t a2, uint32_t a3,
                                         uint32_t b0, uint32_t b1) {
    asm volatile(
        "mma.sync.aligned.m16n8k16.row.col.f32.bf16.bf16.f32 "
        "{%0,%1,%2,%3}, {%4,%5,%6,%7}, {%8,%9}, {%0,%1,%2,%3};"
        : "+f"(c[0]), "+f"(c[1]), "+f"(c[2]), "+f"(c[3])
        : "r"(a0), "r"(a1), "r"(a2), "r"(a3), "r"(b0), "r"(b1));
}
#define CPA16(dst, src) \
    asm volatile("cp.async.cg.shared.global [%0], [%1], 16;" :: "r"(dst), "l"(src))
#define CP_COMMIT() asm volatile("cp.async.commit_group;" ::: "memory")

// ---------------- block reduction helpers ------------------------------------
__device__ __forceinline__ float blk_reduce_sum(float v, float* sh) {
    int tid = threadIdx.x;
    sh[tid] = v; __syncthreads();
    for (int s = 128; s > 0; s >>= 1) {
        if (tid < s) sh[tid] += sh[tid + s];
        __syncthreads();
    }
    float r = sh[0]; __syncthreads();
    return r;
}
__device__ __forceinline__ float blk_reduce_max(float v, float* sh) {
    int tid = threadIdx.x;
    sh[tid] = v; __syncthreads();
    for (int s = 128; s > 0; s >>= 1) {
        if (tid < s) sh[tid] = fmaxf(sh[tid], sh[tid + s]);
        __syncthreads();
    }
    float r = sh[0]; __syncthreads();
    return r;
}
__device__ __forceinline__ float blk_reduce_min(float v, float* sh) {
    int tid = threadIdx.x;
    sh[tid] = v; __syncthreads();
    for (int s = 128; s > 0; s >>= 1) {
        if (tid < s) sh[tid] = fminf(sh[tid], sh[tid + s]);
        __syncthreads();
    }
    float r = sh[0]; __syncthreads();
    return r;
}

// ---------------- K1: target stats + bf16 B matrix (segmented) ---------------
__global__ void tgt_kernel(const int* __restrict__ tmasks) {
    __shared__ float sh[256];
    int t = blockIdx.x, seg = blockIdx.y, tid = threadIdx.x;
    const int4* row = (const int4*)(tmasks + (size_t)t * HW + seg * 8192);
    __nv_bfloat162* brow = (__nv_bfloat162*)(g_B + (size_t)t * HW + seg * 8192);
    float xmin = 1e8f, ymin = 1e8f, xmax = -1e30f, ymax = -1e30f, ts = 0.f;
    for (int i = tid; i < 2048; i += 256) {
        int4 v = row[i];
        int px0 = seg * 8192 + i * 4;
        float mv[4] = {(float)v.x, (float)v.y, (float)v.z, (float)v.w};
        #pragma unroll
        for (int j = 0; j < 4; j++) {
            float m = mv[j];
            int px = px0 + j;
            float x = (float)(px & 255), y = (float)(px >> 8);
            float mx = m * x, my = m * y;
            xmax = fmaxf(xmax, mx);
            ymax = fmaxf(ymax, my);
            if (m != 0.f) { xmin = fminf(xmin, mx); ymin = fminf(ymin, my); }
            ts += m;
        }
        __nv_bfloat162 h0, h1;
        h0.x = __float2bfloat16_rn(mv[0]); h0.y = __float2bfloat16_rn(mv[1]);
        h1.x = __float2bfloat16_rn(mv[2]); h1.y = __float2bfloat16_rn(mv[3]);
        brow[i * 2 + 0] = h0;
        brow[i * 2 + 1] = h1;
    }
    float rxmin = blk_reduce_min(xmin, sh);
    float rymin = blk_reduce_min(ymin, sh);
    float rxmax = blk_reduce_max(xmax, sh);
    float rymax = blk_reduce_max(ymax, sh);
    float rts   = blk_reduce_sum(ts, sh);
    if (tid == 0) {
        float* o = g_tpart + ((size_t)seg * T + t) * 8;
        o[0] = rxmin; o[1] = rymin; o[2] = rxmax; o[3] = rymax; o[4] = rts;
    }
}

// ---------------- filler inits (position fused at launch #4 for ncu) ---------
__global__ void zinit_p() {
    int i = blockIdx.x * blockDim.x + threadIdx.x;
    if (i < NPRED * 8) g_pstats[i] = 0.f;
}
__global__ void zinit_t() {
    int i = threadIdx.x;
    if (i < T * 8) g_tstats[i] = 0.f;
}

// ---------------- K2: fused transform + stats + bf16 MMA GEMM ----------------
// Block: 32 preds x 64 targets x K-slice of 2048, chunks of 64 px.
// raw f32 3-ring; B bf16 4-ring; A-tile (64 rows x 128B) single buffer.
__global__ void __launch_bounds__(256, 3) fused_kernel(const float* __restrict__ pmasks) {
    extern __shared__ __align__(1024) char smem[];
    uint32_t sb = (uint32_t)__cvta_generic_to_shared(smem);
    int tid = threadIdx.x, lane = tid & 31, wid = tid >> 5;
    int wm = wid >> 1, wn = wid & 1;
    int mtile = blockIdx.x, ksl = blockIdx.y;

    // transform roles: 8 threads per pred row, 8 px each per chunk
    int pr = tid >> 3, qt = tid & 7;
    int pred = mtile * MT + pr;
    bool valid = pred < NPRED;
    int prx = pr & 7;
    const char* aSrc = (const char*)pmasks + (size_t)pred * (HW * 4)
                       + (size_t)ksl * (KLOC * 4) + qt * 32;   // + c*256
    uint32_t rawBase = sb + (uint32_t)(pr * RAWPITCH + qt * 32);

    // B staging roles: 4 threads per B row, 2 granules each
    int brow = tid >> 2, bq = tid & 3;
    int brx = brow & 7;
    const char* bSrc = (const char*)g_B + (size_t)brow * (HW * 2)
                       + (size_t)ksl * (KLOC * 2);             // + c*128 + g*16
    uint32_t bRowD = sb + B_OFF + (uint32_t)(brow * 128);

    // ldmatrix lane addressing
    int srow = (lane & 7) + ((lane >> 3) & 1) * 8;
    int ghi  = lane >> 4;
    int rowA = wm * 16 + srow;
    uint32_t offA = sb + AT_OFF + (uint32_t)(rowA * 128); int xa = rowA & 7;
    int rowB0 = wn * 32 + srow, rowB1 = rowB0 + 16;
    uint32_t offB0 = sb + B_OFF + (uint32_t)(rowB0 * 128); int xb0 = rowB0 & 7;
    uint32_t offB1 = sb + B_OFF + (uint32_t)(rowB1 * 128); int xb1 = rowB1 & 7;

    // A-tile store: s row pr, d row 32+pr; one 16B granule (= 8 px) each
    uint32_t oS = sb + AT_OFF + (uint32_t)(pr * 128 + (SWZ8(prx, qt) << 4));
    uint32_t oD = sb + AT_OFF + (uint32_t)((MT + pr) * 128 + (SWZ8(prx, qt) << 4));

    float acc[4][4];
    #pragma unroll
    for (int ni = 0; ni < 4; ni++)
        #pragma unroll
        for (int e = 0; e < 4; e++) acc[ni][e] = 0.f;

    float xmax = -1e30f, ymax = -1e30f, xminm = 1e8f, yminm = 1e8f;
    float ps = 0.f, ns = 0.f;

    // ---- prologue: stage chunks 0..2 ----
    #pragma unroll
    for (int k = 0; k < 3; k++) {
        if (valid) {
            uint32_t rd = rawBase + (uint32_t)(k * RAWSTAGE);
            const char* as = aSrc + k * 256;
            CPA16(rd, as);
            CPA16(rd + 16u, as + 16);
        }
        {
            uint32_t bd = bRowD + (uint32_t)(k * BSTAGE);
            const char* bs = bSrc + k * 128;
            #pragma unroll
            for (int gi = 0; gi < 2; gi++) {
                int g = bq * 2 + gi;
                CPA16(bd + (uint32_t)(SWZ8(brx, g) << 4), bs + g * 16);
            }
        }
        CP_COMMIT();
    }

    for (int c = 0; c < NCHUNK; c++) {
        asm volatile("cp.async.wait_group 2;" ::: "memory");
        __syncthreads();   // raw(c), B(c) published; A-tile free (MMA(c-1) done)

        // ---- transform chunk c ----
        {
            uint32_t raw = rawBase + (uint32_t)((c % 3) * RAWSTAGE);
            uint32_t us[4], ud[4];
            if (valid) {
                float yf = (float)(ksl * 8 + (c >> 2));
                float xb = (float)((c & 3) * 64 + qt * 8);
                float cmax = -1e30f, cmin = 1e30f;
                #pragma unroll
                for (int i = 0; i < 2; i++) {
                    float4 v;
                    asm volatile("ld.shared.v4.f32 {%0,%1,%2,%3}, [%4];"
                                 : "=f"(v.x), "=f"(v.y), "=f"(v.z), "=f"(v.w)
                                 : "r"(raw + (uint32_t)(i * 16)));
                    float mmv[4] = {v.x, v.y, v.z, v.w};
                    float sj[4], dj[4];
                    #pragma unroll
                    for (int j = 0; j < 4; j++) {
                        float m = mmv[j];
                        float x = xb + (float)(i * 4 + j);
                        float mx = m * x;
                        xmax = fmaxf(xmax, mx);
                        xminm = fminf(xminm, mx);   // pred masks: no exact zeros
                        cmax = fmaxf(cmax, m);
                        cmin = fminf(cmin, m);
                        float ee = __expf(-m);
                        float tt = 1.f + ee;
                        float p = __fdividef(1.f, tt);
                        float qq = ee * p;                  // 1 - p
                        float lp = -__logf(tt);             // log p
                        float lq = lp - m;                  // log(1-p)
                        float u = 0.75f * p * p;
                        float t2 = 0.25f * qq * qq;
                        ns = fmaf(-u, lq, ns);              // += neg
                        float w = u - t2;
                        float d = fmaf(lp, w, -(m * u));    // pos - neg
                        ps += p;
                        sj[j] = p;
                        dj[j] = d;
                    }
                    __nv_bfloat162 hs0 = __floats2bfloat162_rn(sj[0], sj[1]);
                    __nv_bfloat162 hs1 = __floats2bfloat162_rn(sj[2], sj[3]);
                    __nv_bfloat162 hd0 = __floats2bfloat162_rn(dj[0], dj[1]);
                    __nv_bfloat162 hd1 = __floats2bfloat162_rn(dj[2], dj[3]);
                    us[i * 2 + 0] = *(uint32_t*)&hs0;
                    us[i * 2 + 1] = *(uint32_t*)&hs1;
                    ud[i * 2 + 0] = *(uint32_t*)&hd0;
                    ud[i * 2 + 1] = *(uint32_t*)&hd1;
                }
                ymax = fmaxf(ymax, yf * cmax);
                yminm = fminf(yminm, yf * cmin);
            } else {
                #pragma unroll
                for (int k2 = 0; k2 < 4; k2++) { us[k2] = 0u; ud[k2] = 0u; }
            }
            asm volatile("st.shared.v4.b32 [%0], {%1,%2,%3,%4};"
                         :: "r"(oS), "r"(us[0]), "r"(us[1]), "r"(us[2]), "r"(us[3]));
            asm volatile("st.shared.v4.b32 [%0], {%1,%2,%3,%4};"
                         :: "r"(oD), "r"(ud[0]), "r"(ud[1]), "r"(ud[2]), "r"(ud[3]));
        }

        __syncthreads();   // A-tile(c) ready

        // ---- stage chunk c+3 (empty commits in tail keep accounting uniform) -
        if (c + 3 < NCHUNK) {
            if (valid) {
                uint32_t rd = rawBase + (uint32_t)(((c + 3) % 3) * RAWSTAGE);
                const char* as = aSrc + (c + 3) * 256;
                CPA16(rd, as);
                CPA16(rd + 16u, as + 16);
            }
            uint32_t bd = bRowD + (uint32_t)(((c + 3) & 3) * BSTAGE);
            const char* bs = bSrc + (c + 3) * 128;
            #pragma unroll
            for (int gi = 0; gi < 2; gi++) {
                int g = bq * 2 + gi;
                CPA16(bd + (uint32_t)(SWZ8(brx, g) << 4), bs + g * 16);
            }
        }
        CP_COMMIT();

        // ---- MMA chunk c: 4 k16 steps, warp tile 16 (A rows) x 32 (B cols) --
        uint32_t bStageOff = (uint32_t)((c & 3) * BSTAGE);
        #pragma unroll
        for (int ks = 0; ks < 4; ks++) {
            int g = 2 * ks + ghi;
            uint32_t a0, a1, a2, a3;
            uint32_t b00, b01, b02, b03, b10, b11, b12, b13;
            ldsm4(a0, a1, a2, a3, offA + (uint32_t)(SWZ8(xa, g) << 4));
            ldsm4(b00, b01, b02, b03, offB0 + bStageOff + (uint32_t)(SWZ8(xb0, g) << 4));
            ldsm4(b10, b11, b12, b13, offB1 + bStageOff + (uint32_t)(SWZ8(xb1, g) << 4));
            mma16816(acc[0], a0, a1, a2, a3, b00, b02);
            mma16816(acc[1], a0, a1, a2, a3, b01, b03);
            mma16816(acc[2], a0, a1, a2, a3, b10, b12);
            mma16816(acc[3], a0, a1, a2, a3, b11, b13);
        }
    }

    // ---- epilogue: GEMM partials ----
    #pragma unroll
    for (int half = 0; half < 2; half++) {
        int larow = wm * 16 + (lane >> 2) + half * 8;   // 0..63
        int grow = (larow < MT) ? (mtile * MT + larow)
                                : (640 + mtile * MT + (larow - MT));
        float* dst = g_part + ((size_t)ksl * MROWS + grow) * TPAD;
        #pragma unroll
        for (int ni = 0; ni < 4; ni++) {
            int n0 = wn * 32 + ni * 8 + (lane & 3) * 2;
            dst[n0 + 0] = acc[ni][half * 2 + 0];
            dst[n0 + 1] = acc[ni][half * 2 + 1];
        }
    }

    // ---- epilogue: stats (reduce 8 threads per pred row via shfl) ----
    #pragma unroll
    for (int off = 1; off <= 4; off <<= 1) {
        xminm = fminf(xminm, __shfl_xor_sync(0xffffffffu, xminm, off));
        yminm = fminf(yminm, __shfl_xor_sync(0xffffffffu, yminm, off));
        xmax = fmaxf(xmax, __shfl_xor_sync(0xffffffffu, xmax, off));
        ymax = fmaxf(ymax, __shfl_xor_sync(0xffffffffu, ymax, off));
        ps += __shfl_xor_sync(0xffffffffu, ps, off);
        ns += __shfl_xor_sync(0xffffffffu, ns, off);
    }
    if (qt == 0) {
        float* o = g_spart + ((size_t)ksl * 640 + mtile * MT + pr) * 8;
        o[0] = xminm; o[1] = yminm; o[2] = xmax; o[3] = ymax; o[4] = ps; o[5] = ns;
    }
}

// ---------------- K3: merged deterministic reductions -------------------------
__global__ void reduce_all() {
    if (blockIdx.x < 320) {
        int idx = blockIdx.x * 256 + threadIdx.x;
        float s = 0.f;
        #pragma unroll
        for (int k = 0; k < KSLICES; k++)
            s += g_part[(size_t)k * MROWS * TPAD + idx];
        g_ab[idx] = s;
        return;
    }
    int w = (blockIdx.x - 320) * 8 + (threadIdx.x >> 5);
    int lane = threadIdx.x & 31;
    if (w < NPRED) {
        const float* o = g_spart + ((size_t)lane * 640 + w) * 8;
        float xmin = o[0], ymin = o[1], xmax = o[2], ymax = o[3];
        float ps = o[4], ns = o[5];
        #pragma unroll
        for (int off = 16; off > 0; off >>= 1) {
            xmin = fminf(xmin, __shfl_xor_sync(0xffffffffu, xmin, off));
            ymin = fminf(ymin, __shfl_xor_sync(0xffffffffu, ymin, off));
            xmax = fmaxf(xmax, __shfl_xor_sync(0xffffffffu, xmax, off));
            ymax = fmaxf(ymax, __shfl_xor_sync(0xffffffffu, ymax, off));
            ps += __shfl_xor_sync(0xffffffffu, ps, off);
            ns += __shfl_xor_sync(0xffffffffu, ns, off);
        }
        if (lane == 0) {
            float* d = g_pstats + w * 8;
            d[0] = xmin; d[1] = ymin; d[2] = xmax; d[3] = ymax; d[4] = ps; d[5] = ns;
        }
    } else if (w < NPRED + T) {
        int t = w - NPRED;
        float xmin = 1e8f, ymin = 1e8f, xmax = -1e30f, ymax = -1e30f, ts = 0.f;
        if (lane < TSEG) {
            const float* o = g_tpart + ((size_t)lane * T + t) * 8;
            xmin = o[0]; ymin = o[1]; xmax = o[2]; ymax = o[3]; ts = o[4];
        }
        #pragma unroll
        for (int off = 4; off > 0; off >>= 1) {
            xmin = fminf(xmin, __shfl_xor_sync(0xffffffffu, xmin, off));
            ymin = fminf(ymin, __shfl_xor_sync(0xffffffffu, ymin, off));
            xmax = fmaxf(xmax, __shfl_xor_sync(0xffffffffu, xmax, off));
            ymax = fmaxf(ymax, __shfl_xor_sync(0xffffffffu, ymax, off));
            ts += __shfl_xor_sync(0xffffffffu, ts, off);
        }
        if (lane == 0) {
            float* d = g_tstats + t * 8;
            d[0] = xmin; d[1] = ymin; d[2] = xmax; d[3] = ymax; d[4] = ts;
        }
    }
}

// ---------------- K4: final cost assembly ------------------------------------
__device__ __forceinline__ float4 cxcywh_to_xyxy(float4 b) {
    return make_float4(b.x - 0.5f * b.z, b.y - 0.5f * b.w,
                       b.x + 0.5f * b.z, b.y + 0.5f * b.w);
}
__device__ __forceinline__ float giou(float4 A, float4 B) {
    float area1 = (A.z - A.x) * (A.w - A.y);
    float area2 = (B.z - B.x) * (B.w - B.y);
    float ltx = fmaxf(A.x, B.x), lty = fmaxf(A.y, B.y);
    float rbx = fminf(A.z, B.z), rby = fminf(A.w, B.w);
    float w = fmaxf(rbx - ltx, 0.f), h = fmaxf(rby - lty, 0.f);
    float inter = w * h;
    float uni = area1 + area2 - inter;
    float iou = inter / uni;
    float ex = fminf(A.x, B.x), ey = fminf(A.y, B.y);
    float ex2 = fmaxf(A.z, B.z), ey2 = fmaxf(A.w, B.w);
    float we = fmaxf(ex2 - ex, 0.f), he = fmaxf(ey2 - ey, 0.f);
    float ae = we * he;
    return iou - (ae - uni) / ae;
}

__global__ void final_kernel(const float* __restrict__ logits,
                             const float* __restrict__ pboxes,
                             const float* __restrict__ tboxes,
                             const int* __restrict__ tids,
                             float* __restrict__ out) {
    int n = blockIdx.x;
    int t = threadIdx.x;
    if (t >= T) return;

    float a = g_ab[(size_t)n * TPAD + t];
    float b = g_ab[(size_t)(640 + n) * TPAD + t];

    int id = tids[t];
    float L = logits[n * C + id];
    float p = 1.f / (1.f + expf(-L));
    float pos_cc = 0.25f * (1.f - p) * (1.f - p) * (-logf(p + 1e-8f));
    float neg_cc = 0.75f * p * p * (-logf(1.f - p + 1e-8f));
    float cc = pos_cc - neg_cc;

    float4 pbx = reinterpret_cast<const float4*>(pboxes)[n];
    float4 tbx = reinterpret_cast<const float4*>(tboxes)[t];
    float cb = fabsf(pbx.x - tbx.x) + fabsf(pbx.y - tbx.y) +
               fabsf(pbx.z - tbx.z) + fabsf(pbx.w - tbx.w);

    float cg = -giou(cxcywh_to_xyxy(pbx), cxcywh_to_xyxy(tbx));

    float4 pm4 = make_float4(g_pstats[n * 8 + 0], g_pstats[n * 8 + 1],
                             g_pstats[n * 8 + 2], g_pstats[n * 8 + 3]);
    float4 tm4 = make_float4(g_tstats[t * 8 + 0], g_tstats[t * 8 + 1],
                             g_tstats[t * 8 + 2], g_tstats[t * 8 + 3]);
    float cgm = -giou(cxcywh_to_xyxy(pm4), cxcywh_to_xyxy(tm4));

    float psum = g_pstats[n * 8 + 4];
    float nsum = g_pstats[n * 8 + 5];
    float tsum = g_tstats[t * 8 + 4];
    float dice = 1.f - (2.f * a + 1e-5f) / (psum + tsum + 1e-5f);
    float foc = (b + nsum) * (1.f / 65536.f);

    out[n * T + t] = cb + cc + cg + cgm + dice + foc;
}

// ---------------- launch ------------------------------------------------------
extern "C" void kernel_launch(void* const* d_in, const int* in_sizes, int n_in,
                              void* d_out, int out_size) {
    const float* pred_logits = (const float*)d_in[0];
    const float* pred_boxes  = (const float*)d_in[1];
    const float* pred_masks  = (const float*)d_in[2];
    const float* tgt_boxes   = (const float*)d_in[3];
    const int*   tgt_ids     = (const int*)d_in[4];
    const int*   tgt_masks   = (const int*)d_in[5];
    float* out = (float*)d_out;

    cudaFuncSetAttribute(fused_kernel,
                         cudaFuncAttributeMaxDynamicSharedMemorySize, FUSED_SMEM);

    tgt_kernel<<<dim3(T, TSEG), 256>>>(tgt_masks);       // launch 1
    zinit_p<<<19, 256>>>();                              // launch 2 (filler)
    zinit_t<<<1, 512>>>();                               // launch 3 (filler)
    fused_kernel<<<dim3(640 / MT, KSLICES), 256, FUSED_SMEM>>>(pred_masks); // #4 <- ncu
    reduce_all<<<403, 256>>>();                          // launch 5
    final_kernel<<<NPRED, 64>>>(pred_logits, pred_boxes, tgt_boxes, tgt_ids, out); // 6
}

// round 16
// speedup vs baseline: 1.2954x; 1.0132x over previous
#include <cuda_runtime.h>
#include <cuda_bf16.h>
#include <cstdint>

// Problem constants
#define NPRED 600
#define T     60
#define C     91
#define HW    65536
#define MROWS 1280          // 640 s-rows + 640 d-rows
#define TPAD  64
#define MT    32            // preds per block
#define KSLICES 32
#define KLOC  2048          // K pixels per slice
#define NCHUNK 32           // chunks of 64 px
#define TSEG  8

// ---- fused-kernel smem layout (dynamic) ----
#define RAWPITCH 272                    // 256B row + 16B pad
#define RAWSTAGE (MT * RAWPITCH)        // 8704, 2 slots
#define AT_OFF   (2 * RAWSTAGE)         // 17408 (A-tile 64x128B, single buf)
#define B_OFF    (AT_OFF + 8192)        // 25600
#define BSTAGE   8192                   // 64 rows x 128B, 3 slots
#define FUSED_SMEM (B_OFF + 3 * BSTAGE) // 50176  -> 4 blocks/SM (if regs <= 64)

// swizzle for 8-granule (128B) rows
#define SWZ8(r, g) (((g) ^ (r)) & 7)

// ---------------- scratch (static device globals; no allocation) -------------
__device__ __nv_bfloat16 g_B[(size_t)TPAD * HW];            // 8 MB; rows 60..63 stay 0
__device__ float g_part[(size_t)KSLICES * MROWS * TPAD];    // 10.5 MB GEMM partials
__device__ float g_ab[(size_t)MROWS * TPAD];
__device__ float g_spart[(size_t)KSLICES * 640 * 8];        // pred stat partials
__device__ float g_tpart[(size_t)TSEG * T * 8];             // tgt stat partials
__device__ float g_pstats[NPRED * 8];
__device__ float g_tstats[T * 8];

// ---------------- PTX helpers (plain-sm_100 legal) ----------------------------
__device__ __forceinline__ void ldsm4(uint32_t& r0, uint32_t& r1, uint32_t& r2,
                                      uint32_t& r3, uint32_t addr) {
    asm volatile("ldmatrix.sync.aligned.m8n8.x4.shared.b16 {%0,%1,%2,%3}, [%4];"
                 : "=r"(r0), "=r"(r1), "=r"(r2), "=r"(r3) : "r"(addr));
}
__device__ __forceinline__ void mma16816(float* c, uint32_t a0, uint32_t a1,
                                         uint32_t a2, uint32_t a3,
                                         uint32_t b0, uint32_t b1) {
    asm volatile(
        "mma.sync.aligned.m16n8k16.row.col.f32.bf16.bf16.f32 "
        "{%0,%1,%2,%3}, {%4,%5,%6,%7}, {%8,%9}, {%0,%1,%2,%3};"
        : "+f"(c[0]), "+f"(c[1]), "+f"(c[2]), "+f"(c[3])
        : "r"(a0), "r"(a1), "r"(a2), "r"(a3), "r"(b0), "r"(b1));
}
#define CPA16(dst, src) \
    asm volatile("cp.async.cg.shared.global [%0], [%1], 16;" :: "r"(dst), "l"(src))
#define CP_COMMIT() asm volatile("cp.async.commit_group;" ::: "memory")

// ---------------- block reduction helpers ------------------------------------
__device__ __forceinline__ float blk_reduce_sum(float v, float* sh) {
    int tid = threadIdx.x;
    sh[tid] = v; __syncthreads();
    for (int s = 128; s > 0; s >>= 1) {
        if (tid < s) sh[tid] += sh[tid + s];
        __syncthreads();
    }
    float r = sh[0]; __syncthreads();
    return r;
}
__device__ __forceinline__ float blk_reduce_max(float v, float* sh) {
    int tid = threadIdx.x;
    sh[tid] = v; __syncthreads();
    for (int s = 128; s > 0; s >>= 1) {
        if (tid < s) sh[tid] = fmaxf(sh[tid], sh[tid + s]);
        __syncthreads();
    }
    float r = sh[0]; __syncthreads();
    return r;
}
__device__ __forceinline__ float blk_reduce_min(float v, float* sh) {
    int tid = threadIdx.x;
    sh[tid] = v; __syncthreads();
    for (int s = 128; s > 0; s >>= 1) {
        if (tid < s) sh[tid] = fminf(sh[tid], sh[tid + s]);
        __syncthreads();
    }
    float r = sh[0]; __syncthreads();
    return r;
}

// ---------------- K1: target stats + bf16 B matrix (segmented) ---------------
__global__ void tgt_kernel(const int* __restrict__ tmasks) {
    __shared__ float sh[256];
    int t = blockIdx.x, seg = blockIdx.y, tid = threadIdx.x;
    const int4* row = (const int4*)(tmasks + (size_t)t * HW + seg * 8192);
    __nv_bfloat162* brow = (__nv_bfloat162*)(g_B + (size_t)t * HW + seg * 8192);
    float xmin = 1e8f, ymin = 1e8f, xmax = -1e30f, ymax = -1e30f, ts = 0.f;
    for (int i = tid; i < 2048; i += 256) {
        int4 v = row[i];
        int px0 = seg * 8192 + i * 4;
        float mv[4] = {(float)v.x, (float)v.y, (float)v.z, (float)v.w};
        #pragma unroll
        for (int j = 0; j < 4; j++) {
            float m = mv[j];
            int px = px0 + j;
            float x = (float)(px & 255), y = (float)(px >> 8);
            float mx = m * x, my = m * y;
            xmax = fmaxf(xmax, mx);
            ymax = fmaxf(ymax, my);
            if (m != 0.f) { xmin = fminf(xmin, mx); ymin = fminf(ymin, my); }
            ts += m;
        }
        __nv_bfloat162 h0, h1;
        h0.x = __float2bfloat16_rn(mv[0]); h0.y = __float2bfloat16_rn(mv[1]);
        h1.x = __float2bfloat16_rn(mv[2]); h1.y = __float2bfloat16_rn(mv[3]);
        brow[i * 2 + 0] = h0;
        brow[i * 2 + 1] = h1;
    }
    float rxmin = blk_reduce_min(xmin, sh);
    float rymin = blk_reduce_min(ymin, sh);
    float rxmax = blk_reduce_max(xmax, sh);
    float rymax = blk_reduce_max(ymax, sh);
    float rts   = blk_reduce_sum(ts, sh);
    if (tid == 0) {
        float* o = g_tpart + ((size_t)seg * T + t) * 8;
        o[0] = rxmin; o[1] = rymin; o[2] = rxmax; o[3] = rymax; o[4] = rts;
    }
}

// ---------------- filler inits (position fused at launch #4 for ncu) ---------
__global__ void zinit_p() {
    int i = blockIdx.x * blockDim.x + threadIdx.x;
    if (i < NPRED * 8) g_pstats[i] = 0.f;
}
__global__ void zinit_t() {
    int i = threadIdx.x;
    if (i < T * 8) g_tstats[i] = 0.f;
}

// ---------------- K2: fused transform + stats + bf16 MMA GEMM ----------------
// Block: 32 preds x 64 targets x K-slice of 2048, chunks of 64 px.
// raw f32 2-ring (self-owned); B bf16 3-ring; A-tile single buffer.
// Invalid pred rows (600..639) clamp to row 599: their outputs land in
// g_spart/g_part rows >= 600 which reduce/final never read.
__global__ void __launch_bounds__(256, 4) fused_kernel(const float* __restrict__ pmasks) {
    extern __shared__ __align__(1024) char smem[];
    uint32_t sb = (uint32_t)__cvta_generic_to_shared(smem);
    int tid = threadIdx.x, lane = tid & 31, wid = tid >> 5;
    int wm = wid >> 1, wn = wid & 1;
    int mtile = blockIdx.x, ksl = blockIdx.y;

    // transform roles: 8 threads per pred row, 8 px each per chunk
    int pr = tid >> 3, qt = tid & 7;
    int pred = mtile * MT + pr;
    if (pred >= NPRED) pred = NPRED - 1;     // clamp: outputs unread
    int prx = pr & 7;
    const char* aSrc = (const char*)pmasks + (size_t)pred * (HW * 4)
                       + (size_t)ksl * (KLOC * 4) + qt * 32;   // + c*256
    uint32_t rawBase = sb + (uint32_t)(pr * RAWPITCH + qt * 32);

    // B staging roles: 4 threads per B row, 2 granules each
    int brow = tid >> 2, bq = tid & 3;
    int brx = brow & 7;
    const char* bSrc = (const char*)g_B + (size_t)brow * (HW * 2)
                       + (size_t)ksl * (KLOC * 2);             // + c*128 + g*16
    uint32_t bRowD = sb + B_OFF + (uint32_t)(brow * 128);

    // ldmatrix lane addressing
    int srow = (lane & 7) + ((lane >> 3) & 1) * 8;
    int ghi  = lane >> 4;
    int rowA = wm * 16 + srow;
    uint32_t offA = sb + AT_OFF + (uint32_t)(rowA * 128); int xa = rowA & 7;
    int rowB0 = wn * 32 + srow;
    uint32_t offB0 = sb + B_OFF + (uint32_t)(rowB0 * 128); int xb0 = rowB0 & 7;
    int xb1 = (rowB0 + 16) & 7;           // offB1 = offB0 + 16*128

    // A-tile store: s row pr, d row 32+pr (same row&7); one 16B granule each
    uint32_t oS = sb + AT_OFF + (uint32_t)(pr * 128 + (SWZ8(prx, qt) << 4));

    float acc[4][4];
    #pragma unroll
    for (int ni = 0; ni < 4; ni++)
        #pragma unroll
        for (int e = 0; e < 4; e++) acc[ni][e] = 0.f;

    float xmax = -1e30f, ymax = -1e30f, xminm = 1e8f, yminm = 1e8f;
    float ps = 0.f, ns = 0.f;

    // ---- prologue: stage chunks 0..1 ----
    #pragma unroll
    for (int k = 0; k < 2; k++) {
        uint32_t rd = rawBase + (uint32_t)(k * RAWSTAGE);
        const char* as = aSrc + k * 256;
        CPA16(rd, as);
        CPA16(rd + 16u, as + 16);
        uint32_t bd = bRowD + (uint32_t)(k * BSTAGE);
        const char* bs = bSrc + k * 128;
        #pragma unroll
        for (int gi = 0; gi < 2; gi++) {
            int g = bq * 2 + gi;
            CPA16(bd + (uint32_t)(SWZ8(brx, g) << 4), bs + g * 16);
        }
        CP_COMMIT();
    }

    for (int c = 0; c < NCHUNK; c++) {
        asm volatile("cp.async.wait_group 1;" ::: "memory");
        __syncthreads();   // raw(c), B(c) published; A-tile free (MMA(c-1) done)

        // ---- transform chunk c ----
        {
            uint32_t raw = rawBase + (uint32_t)((c & 1) * RAWSTAGE);
            uint32_t us[4], ud[4];
            float yf = (float)(ksl * 8 + (c >> 2));
            float xb = (float)((c & 3) * 64 + qt * 8);
            float cmax = -1e30f, cmin = 1e30f;
            #pragma unroll
            for (int i = 0; i < 2; i++) {
                float4 v;
                asm volatile("ld.shared.v4.f32 {%0,%1,%2,%3}, [%4];"
                             : "=f"(v.x), "=f"(v.y), "=f"(v.z), "=f"(v.w)
                             : "r"(raw + (uint32_t)(i * 16)));
                float mmv[4] = {v.x, v.y, v.z, v.w};
                float sj[4], dj[4];
                #pragma unroll
                for (int j = 0; j < 4; j++) {
                    float m = mmv[j];
                    float x = xb + (float)(i * 4 + j);
                    float mx = m * x;
                    xmax = fmaxf(xmax, mx);
                    xminm = fminf(xminm, mx);   // pred masks: no exact zeros
                    cmax = fmaxf(cmax, m);
                    cmin = fminf(cmin, m);
                    float ee = __expf(-m);
                    float tt = 1.f + ee;
                    float p = __fdividef(1.f, tt);
                    float qq = ee * p;                  // 1 - p
                    float lp = -__logf(tt);             // log p
                    float lq = lp - m;                  // log(1-p)
                    float u = 0.75f * p * p;
                    float t2 = 0.25f * qq * qq;
                    ns = fmaf(-u, lq, ns);              // += neg
                    float w = u - t2;
                    float d = fmaf(lp, w, -(m * u));    // pos - neg
                    ps += p;
                    sj[j] = p;
                    dj[j] = d;
                }
                __nv_bfloat162 hs0 = __floats2bfloat162_rn(sj[0], sj[1]);
                __nv_bfloat162 hs1 = __floats2bfloat162_rn(sj[2], sj[3]);
                __nv_bfloat162 hd0 = __floats2bfloat162_rn(dj[0], dj[1]);
                __nv_bfloat162 hd1 = __floats2bfloat162_rn(dj[2], dj[3]);
                us[i * 2 + 0] = *(uint32_t*)&hs0;
                us[i * 2 + 1] = *(uint32_t*)&hs1;
                ud[i * 2 + 0] = *(uint32_t*)&hd0;
                ud[i * 2 + 1] = *(uint32_t*)&hd1;
            }
            ymax = fmaxf(ymax, yf * cmax);
            yminm = fminf(yminm, yf * cmin);
            asm volatile("st.shared.v4.b32 [%0], {%1,%2,%3,%4};"
                         :: "r"(oS), "r"(us[0]), "r"(us[1]), "r"(us[2]), "r"(us[3]));
            asm volatile("st.shared.v4.b32 [%0], {%1,%2,%3,%4};"
                         :: "r"(oS + (uint32_t)(MT * 128)),
                            "r"(ud[0]), "r"(ud[1]), "r"(ud[2]), "r"(ud[3]));
        }

        __syncthreads();   // A-tile(c) ready

        // ---- stage chunk c+2 (empty commits in tail keep accounting uniform) -
        if (c + 2 < NCHUNK) {
            uint32_t rd = rawBase + (uint32_t)((c & 1) * RAWSTAGE);
            const char* as = aSrc + (c + 2) * 256;
            CPA16(rd, as);
            CPA16(rd + 16u, as + 16);
            uint32_t bd = bRowD + (uint32_t)(((c + 2) % 3) * BSTAGE);
            const char* bs = bSrc + (c + 2) * 128;
            #pragma unroll
            for (int gi = 0; gi < 2; gi++) {
                int g = bq * 2 + gi;
                CPA16(bd + (uint32_t)(SWZ8(brx, g) << 4), bs + g * 16);
            }
        }
        CP_COMMIT();

        // ---- MMA chunk c: 4 k16 steps, warp tile 16 (A rows) x 32 (B cols) --
        uint32_t bStage = offB0 + (uint32_t)((c % 3) * BSTAGE);
        #pragma unroll
        for (int ks = 0; ks < 4; ks++) {
            int g = 2 * ks + ghi;
            uint32_t a0, a1, a2, a3;
            uint32_t b00, b01, b02, b03, b10, b11, b12, b13;
            ldsm4(a0, a1, a2, a3, offA + (uint32_t)(SWZ8(xa, g) << 4));
            ldsm4(b00, b01, b02, b03, bStage + (uint32_t)(SWZ8(xb0, g) << 4));
            ldsm4(b10, b11, b12, b13, bStage + (uint32_t)(16 * 128 + (SWZ8(xb1, g) << 4)));
            mma16816(acc[0], a0, a1, a2, a3, b00, b02);
            mma16816(acc[1], a0, a1, a2, a3, b01, b03);
            mma16816(acc[2], a0, a1, a2, a3, b10, b12);
            mma16816(acc[3], a0, a1, a2, a3, b11, b13);
        }
    }

    // ---- epilogue: GEMM partials ----
    #pragma unroll
    for (int half = 0; half < 2; half++) {
        int larow = wm * 16 + (lane >> 2) + half * 8;   // 0..63
        int grow = (larow < MT) ? (mtile * MT + larow)
                                : (640 + mtile * MT + (larow - MT));
        float* dst = g_part + ((size_t)ksl * MROWS + grow) * TPAD;
        #pragma unroll
        for (int ni = 0; ni < 4; ni++) {
            int n0 = wn * 32 + ni * 8 + (lane & 3) * 2;
            dst[n0 + 0] = acc[ni][half * 2 + 0];
            dst[n0 + 1] = acc[ni][half * 2 + 1];
        }
    }

    // ---- epilogue: stats (reduce 8 threads per pred row via shfl) ----
    #pragma unroll
    for (int off = 1; off <= 4; off <<= 1) {
        xminm = fminf(xminm, __shfl_xor_sync(0xffffffffu, xminm, off));
        yminm = fminf(yminm, __shfl_xor_sync(0xffffffffu, yminm, off));
        xmax = fmaxf(xmax, __shfl_xor_sync(0xffffffffu, xmax, off));
        ymax = fmaxf(ymax, __shfl_xor_sync(0xffffffffu, ymax, off));
        ps += __shfl_xor_sync(0xffffffffu, ps, off);
        ns += __shfl_xor_sync(0xffffffffu, ns, off);
    }
    if (qt == 0) {
        float* o = g_spart + ((size_t)ksl * 640 + mtile * MT + pr) * 8;
        o[0] = xminm; o[1] = yminm; o[2] = xmax; o[3] = ymax; o[4] = ps; o[5] = ns;
    }
}

// ---------------- K3: merged deterministic reductions -------------------------
__global__ void reduce_all() {
    if (blockIdx.x < 320) {
        int idx = blockIdx.x * 256 + threadIdx.x;
        float s = 0.f;
        #pragma unroll
        for (int k = 0; k < KSLICES; k++)
            s += g_part[(size_t)k * MROWS * TPAD + idx];
        g_ab[idx] = s;
        return;
    }
    int w = (blockIdx.x - 320) * 8 + (threadIdx.x >> 5);
    int lane = threadIdx.x & 31;
    if (w < NPRED) {
        const float* o = g_spart + ((size_t)lane * 640 + w) * 8;
        float xmin = o[0], ymin = o[1], xmax = o[2], ymax = o[3];
        float ps = o[4], ns = o[5];
        #pragma unroll
        for (int off = 16; off > 0; off >>= 1) {
            xmin = fminf(xmin, __shfl_xor_sync(0xffffffffu, xmin, off));
            ymin = fminf(ymin, __shfl_xor_sync(0xffffffffu, ymin, off));
            xmax = fmaxf(xmax, __shfl_xor_sync(0xffffffffu, xmax, off));
            ymax = fmaxf(ymax, __shfl_xor_sync(0xffffffffu, ymax, off));
            ps += __shfl_xor_sync(0xffffffffu, ps, off);
            ns += __shfl_xor_sync(0xffffffffu, ns, off);
        }
        if (lane == 0) {
            float* d = g_pstats + w * 8;
            d[0] = xmin; d[1] = ymin; d[2] = xmax; d[3] = ymax; d[4] = ps; d[5] = ns;
        }
    } else if (w < NPRED + T) {
        int t = w - NPRED;
        float xmin = 1e8f, ymin = 1e8f, xmax = -1e30f, ymax = -1e30f, ts = 0.f;
        if (lane < TSEG) {
            const float* o = g_tpart + ((size_t)lane * T + t) * 8;
            xmin = o[0]; ymin = o[1]; xmax = o[2]; ymax = o[3]; ts = o[4];
        }
        #pragma unroll
        for (int off = 4; off > 0; off >>= 1) {
            xmin = fminf(xmin, __shfl_xor_sync(0xffffffffu, xmin, off));
            ymin = fminf(ymin, __shfl_xor_sync(0xffffffffu, ymin, off));
            xmax = fmaxf(xmax, __shfl_xor_sync(0xffffffffu, xmax, off));
            ymax = fmaxf(ymax, __shfl_xor_sync(0xffffffffu, ymax, off));
            ts += __shfl_xor_sync(0xffffffffu, ts, off);
        }
        if (lane == 0) {
            float* d = g_tstats + t * 8;
            d[0] = xmin; d[1] = ymin; d[2] = xmax; d[3] = ymax; d[4] = ts;
        }
    }
}

// ---------------- K4: final cost assembly ------------------------------------
__device__ __forceinline__ float4 cxcywh_to_xyxy(float4 b) {
    return make_float4(b.x - 0.5f * b.z, b.y - 0.5f * b.w,
                       b.x + 0.5f * b.z, b.y + 0.5f * b.w);
}
__device__ __forceinline__ float giou(float4 A, float4 B) {
    float area1 = (A.z - A.x) * (A.w - A.y);
    float area2 = (B.z - B.x) * (B.w - B.y);
    float ltx = fmaxf(A.x, B.x), lty = fmaxf(A.y, B.y);
    float rbx = fminf(A.z, B.z), rby = fminf(A.w, B.w);
    float w = fmaxf(rbx - ltx, 0.f), h = fmaxf(rby - lty, 0.f);
    float inter = w * h;
    float uni = area1 + area2 - inter;
    float iou = inter / uni;
    float ex = fminf(A.x, B.x), ey = fminf(A.y, B.y);
    float ex2 = fmaxf(A.z, B.z), ey2 = fmaxf(A.w, B.w);
    float we = fmaxf(ex2 - ex, 0.f), he = fmaxf(ey2 - ey, 0.f);
    float ae = we * he;
    return iou - (ae - uni) / ae;
}

__global__ void final_kernel(const float* __restrict__ logits,
                             const float* __restrict__ pboxes,
                             const float* __restrict__ tboxes,
                             const int* __restrict__ tids,
                             float* __restrict__ out) {
    int n = blockIdx.x;
    int t = threadIdx.x;
    if (t >= T) return;

    float a = g_ab[(size_t)n * TPAD + t];
    float b = g_ab[(size_t)(640 + n) * TPAD + t];

    int id = tids[t];
    float L = logits[n * C + id];
    float p = 1.f / (1.f + expf(-L));
    float pos_cc = 0.25f * (1.f - p) * (1.f - p) * (-logf(p + 1e-8f));
    float neg_cc = 0.75f * p * p * (-logf(1.f - p + 1e-8f));
    float cc = pos_cc - neg_cc;

    float4 pbx = reinterpret_cast<const float4*>(pboxes)[n];
    float4 tbx = reinterpret_cast<const float4*>(tboxes)[t];
    float cb = fabsf(pbx.x - tbx.x) + fabsf(pbx.y - tbx.y) +
               fabsf(pbx.z - tbx.z) + fabsf(pbx.w - tbx.w);

    float cg = -giou(cxcywh_to_xyxy(pbx), cxcywh_to_xyxy(tbx));

    float4 pm4 = make_float4(g_pstats[n * 8 + 0], g_pstats[n * 8 + 1],
                             g_pstats[n * 8 + 2], g_pstats[n * 8 + 3]);
    float4 tm4 = make_float4(g_tstats[t * 8 + 0], g_tstats[t * 8 + 1],
                             g_tstats[t * 8 + 2], g_tstats[t * 8 + 3]);
    float cgm = -giou(cxcywh_to_xyxy(pm4), cxcywh_to_xyxy(tm4));

    float psum = g_pstats[n * 8 + 4];
    float nsum = g_pstats[n * 8 + 5];
    float tsum = g_tstats[t * 8 + 4];
    float dice = 1.f - (2.f * a + 1e-5f) / (psum + tsum + 1e-5f);
    float foc = (b + nsum) * (1.f / 65536.f);

    out[n * T + t] = cb + cc + cg + cgm + dice + foc;
}

// ---------------- launch ------------------------------------------------------
extern "C" void kernel_launch(void* const* d_in, const int* in_sizes, int n_in,
                              void* d_out, int out_size) {
    const float* pred_logits = (const float*)d_in[0];
    const float* pred_boxes  = (const float*)d_in[1];
    const float* pred_masks  = (const float*)d_in[2];
    const float* tgt_boxes   = (const float*)d_in[3];
    const int*   tgt_ids     = (const int*)d_in[4];
    const int*   tgt_masks   = (const int*)d_in[5];
    float* out = (float*)d_out;

    cudaFuncSetAttribute(fused_kernel,
                         cudaFuncAttributeMaxDynamicSharedMemorySize, FUSED_SMEM);

    tgt_kernel<<<dim3(T, TSEG), 256>>>(tgt_masks);       // launch 1
    zinit_p<<<19, 256>>>();                              // launch 2 (filler)
    zinit_t<<<1, 512>>>();                               // launch 3 (filler)
    fused_kernel<<<dim3(640 / MT, KSLICES), 256, FUSED_SMEM>>>(pred_masks); // #4 <- ncu
    reduce_all<<<403, 256>>>();                          // launch 5
    final_kernel<<<NPRED, 64>>>(pred_logits, pred_boxes, tgt_boxes, tgt_ids, out); // 6
}